// round 1
// baseline (speedup 1.0000x reference)
#include <cuda_runtime.h>
#include <cuda_bf16.h>
#include <cstdio>

// ---------------------------------------------------------------------------
// SparseGraphSAGE on GB300.
// Pipeline per launch (all on default stream, graph-capturable):
//   1. zero per-row edge counters
//   2. bucket-scatter edges into fixed-capacity per-row lists (int atomics only)
//   3. spmm gather pass 1 (h -> t), also computes deg_inv
//   4. GEMM: h1 = relu((t * deg_inv) @ W1 + b1)
//   5. spmm gather pass 2 (h1 -> t)
//   6. GEMM: h2 = (t * deg_inv) @ W2 + b2        (written directly to d_out)
//   7. GEMM: P = h2 @ Wd1[:128]                  (decoder factorization)
//   8. GEMM: Q = h2 @ Wd1[128:]
//   9. decode pos: score = relu(P[u]+Q[v]+bd1) . Wd2 + bd2
//  10. decode neg
// ---------------------------------------------------------------------------

#define NN_MAX 50000
#define CAP 64          // per-row edge capacity; mean deg=16, P(>64) ~ 1e-19

__device__ int   g_cnt[NN_MAX];
__device__ int   g_col[NN_MAX * CAP];
__device__ float g_val[NN_MAX * CAP];
__device__ float g_deginv[NN_MAX];
__device__ __align__(16) float g_t [NN_MAX * 128];
__device__ __align__(16) float g_h1[NN_MAX * 128];
__device__ __align__(16) float g_P [NN_MAX * 128];
__device__ __align__(16) float g_Q [NN_MAX * 128];

// -------------------------------- zero counters ---------------------------
__global__ void k_zero_cnt(int nn) {
    int i = blockIdx.x * blockDim.x + threadIdx.x;
    if (i < nn) g_cnt[i] = 0;
}

// -------------------------------- bucket scatter --------------------------
__global__ void k_build(const int2* __restrict__ idx, const float* __restrict__ val, int ne) {
    int e = blockIdx.x * blockDim.x + threadIdx.x;
    if (e >= ne) return;
    int2 rc = idx[e];
    float v = val[e];
    int slot = atomicAdd(&g_cnt[rc.x], 1);
    if (slot < CAP) {
        g_col[rc.x * CAP + slot] = rc.y;
        g_val[rc.x * CAP + slot] = v;
    }
}

// -------------------------------- spmm gather -----------------------------
// One warp per row. Lane f handles features [4f, 4f+4).
__global__ void k_spmm(const float4* __restrict__ X, float4* __restrict__ Y,
                       float* __restrict__ deginv_out, int nn) {
    int w = (blockIdx.x * blockDim.x + threadIdx.x) >> 5;
    int lane = threadIdx.x & 31;
    if (w >= nn) return;
    int cnt = g_cnt[w];
    if (cnt > CAP) cnt = CAP;
    const int*   cols = &g_col[w * CAP];
    const float* vals = &g_val[w * CAP];
    float4 acc = make_float4(0.f, 0.f, 0.f, 0.f);
    float dsum = 0.f;
#pragma unroll 2
    for (int e = 0; e < cnt; e++) {
        int c = cols[e];
        float v = vals[e];
        float4 x = X[c * 32 + lane];
        acc.x += v * x.x; acc.y += v * x.y; acc.z += v * x.z; acc.w += v * x.w;
        dsum += v;
    }
    Y[w * 32 + lane] = acc;
    if (deginv_out != nullptr && lane == 0)
        deginv_out[w] = 1.0f / fmaxf(dsum, 1.0f);
}

// -------------------------------- node GEMM -------------------------------
// C[M,128] = f( (A[M,128] * scale[m]?) @ W[128,128] + b? ), f = relu?
// Block: 64 rows x 128 cols, 256 threads, 8x4 register tile per thread.
template <bool RELU, bool SCALE, bool BIAS>
__global__ void k_gemm(const float* __restrict__ A, const float* __restrict__ scale,
                       const float* __restrict__ W, const float* __restrict__ bias,
                       float* __restrict__ C, int M) {
    extern __shared__ float sm[];
    float* Ws = sm;              // 128*128
    float* As = sm + 128 * 128;  // 64*128
    int tid = threadIdx.x;

    // Load W (4096 float4, 16 per thread)
    const float4* W4 = (const float4*)W;
    float4* Ws4 = (float4*)Ws;
#pragma unroll
    for (int i = 0; i < 16; i++)
        Ws4[i * 256 + tid] = W4[i * 256 + tid];

    // Load A tile (2048 float4, 8 per thread), scaled
    int m_base = blockIdx.x * 64;
    const float4* A4 = (const float4*)A;
    float4* As4 = (float4*)As;
#pragma unroll
    for (int i = 0; i < 8; i++) {
        int j = i * 256 + tid;        // 0..2047
        int m = j >> 5;               // row within tile
        int gm = m_base + m;
        int gmc = gm < M ? gm : (M - 1);
        float4 v = A4[gmc * 32 + (j & 31)];
        if (SCALE) {
            float s = scale[gmc];
            v.x *= s; v.y *= s; v.z *= s; v.w *= s;
        }
        As4[j] = v;
    }
    __syncthreads();

    int tx = tid & 31;     // -> n0 = tx*4
    int ty = tid >> 5;     // -> m0 = ty*8
    int n0 = tx * 4, m0 = ty * 8;

    float acc[8][4];
#pragma unroll
    for (int i = 0; i < 8; i++)
#pragma unroll
        for (int j = 0; j < 4; j++) acc[i][j] = 0.f;

#pragma unroll 4
    for (int k = 0; k < 128; k++) {
        float4 w = *(const float4*)&Ws[k * 128 + n0];
#pragma unroll
        for (int i = 0; i < 8; i++) {
            float a = As[(m0 + i) * 128 + k];
            acc[i][0] += a * w.x;
            acc[i][1] += a * w.y;
            acc[i][2] += a * w.z;
            acc[i][3] += a * w.w;
        }
    }

    float4 bv = make_float4(0.f, 0.f, 0.f, 0.f);
    if (BIAS) bv = *(const float4*)&bias[n0];
#pragma unroll
    for (int i = 0; i < 8; i++) {
        int gm = m_base + m0 + i;
        if (gm < M) {
            float4 r;
            r.x = acc[i][0] + bv.x;
            r.y = acc[i][1] + bv.y;
            r.z = acc[i][2] + bv.z;
            r.w = acc[i][3] + bv.w;
            if (RELU) {
                r.x = fmaxf(r.x, 0.f); r.y = fmaxf(r.y, 0.f);
                r.z = fmaxf(r.z, 0.f); r.w = fmaxf(r.w, 0.f);
            }
            *(float4*)&C[gm * 128 + n0] = r;
        }
    }
}

// -------------------------------- decoder ---------------------------------
// One warp per pair: score = relu(P[u]+Q[v]+bd1) . Wd2 + bd2
__global__ void k_decode(const int* __restrict__ U, const int* __restrict__ V,
                         const float4* __restrict__ P, const float4* __restrict__ Q,
                         const float* __restrict__ bd1, const float* __restrict__ Wd2,
                         const float* __restrict__ bd2, float* __restrict__ out, int M) {
    int w = (blockIdx.x * blockDim.x + threadIdx.x) >> 5;
    int lane = threadIdx.x & 31;
    if (w >= M) return;
    int u = U[w], v = V[w];
    float4 p = P[u * 32 + lane];
    float4 q = Q[v * 32 + lane];
    float4 b = ((const float4*)bd1)[lane];
    float4 d = ((const float4*)Wd2)[lane];
    float h0 = fmaxf(p.x + q.x + b.x, 0.f);
    float h1 = fmaxf(p.y + q.y + b.y, 0.f);
    float h2 = fmaxf(p.z + q.z + b.z, 0.f);
    float h3 = fmaxf(p.w + q.w + b.w, 0.f);
    float s = h0 * d.x + h1 * d.y + h2 * d.z + h3 * d.w;
#pragma unroll
    for (int o = 16; o > 0; o >>= 1)
        s += __shfl_down_sync(0xffffffff, s, o);
    if (lane == 0) out[w] = s + bd2[0];
}

// -------------------------------- launcher --------------------------------
extern "C" void kernel_launch(void* const* d_in, const int* in_sizes, int n_in,
                              void* d_out, int out_size) {
    // Input layout: adj_indices, adj_values, [num_nodes], h, pos_u, pos_v,
    //               neg_u, neg_v, W1, b1, W2, b2, Wd1, bd1, Wd2, bd2
    int o = (n_in >= 16) ? 1 : 0;   // num_nodes scalar present?

    const int2*  adj   = (const int2*) d_in[0];
    const float* avals = (const float*)d_in[1];
    const float* h     = (const float*)d_in[2 + o];
    const int*   pos_u = (const int*)  d_in[3 + o];
    const int*   pos_v = (const int*)  d_in[4 + o];
    const int*   neg_u = (const int*)  d_in[5 + o];
    const int*   neg_v = (const int*)  d_in[6 + o];
    const float* W1    = (const float*)d_in[7 + o];
    const float* b1    = (const float*)d_in[8 + o];
    const float* W2    = (const float*)d_in[9 + o];
    const float* b2    = (const float*)d_in[10 + o];
    const float* Wd1   = (const float*)d_in[11 + o];
    const float* bd1   = (const float*)d_in[12 + o];
    const float* Wd2   = (const float*)d_in[13 + o];
    const float* bd2   = (const float*)d_in[14 + o];

    const int NE = in_sizes[1];
    const int NN = in_sizes[2 + o] / 128;
    const int NP = in_sizes[3 + o];

    float* out = (float*)d_out;
    float* pos_out = out;
    float* neg_out = out + NP;
    float* h2      = out + 2 * NP;   // [NN,128], 16B-aligned (2*NP*4 % 16 == 0)

    // Device-global scratch symbol addresses (host-side, no allocation)
    static float* p_t = nullptr;
    static float* p_h1 = nullptr;
    static float* p_P = nullptr;
    static float* p_Q = nullptr;
    static float* p_deginv = nullptr;
    static bool init = false;
    if (!init) {
        cudaGetSymbolAddress((void**)&p_t, g_t);
        cudaGetSymbolAddress((void**)&p_h1, g_h1);
        cudaGetSymbolAddress((void**)&p_P, g_P);
        cudaGetSymbolAddress((void**)&p_Q, g_Q);
        cudaGetSymbolAddress((void**)&p_deginv, g_deginv);
        // opt in to 96KB dynamic smem for the GEMM instantiations
        cudaFuncSetAttribute(k_gemm<true,  true,  true >, cudaFuncAttributeMaxDynamicSharedMemorySize, 96 * 1024);
        cudaFuncSetAttribute(k_gemm<false, true,  true >, cudaFuncAttributeMaxDynamicSharedMemorySize, 96 * 1024);
        cudaFuncSetAttribute(k_gemm<false, false, false>, cudaFuncAttributeMaxDynamicSharedMemorySize, 96 * 1024);
        init = true;
    }

    const int GEMM_SMEM = 96 * 1024;
    int gemm_blocks = (NN + 63) / 64;

    // 1. zero counters
    k_zero_cnt<<<(NN + 255) / 256, 256>>>(NN);
    // 2. bucket scatter
    k_build<<<(NE + 255) / 256, 256>>>(adj, avals, NE);
    // 3. spmm(h) -> t, deg_inv
    k_spmm<<<(NN * 32 + 255) / 256, 256>>>((const float4*)h, (float4*)p_t, p_deginv, NN);
    // 4. h1 = relu((t*deg_inv)@W1 + b1)
    k_gemm<true, true, true><<<gemm_blocks, 256, GEMM_SMEM>>>(p_t, p_deginv, W1, b1, p_h1, NN);
    // 5. spmm(h1) -> t
    k_spmm<<<(NN * 32 + 255) / 256, 256>>>((const float4*)p_h1, (float4*)p_t, nullptr, NN);
    // 6. h2 = (t*deg_inv)@W2 + b2   (straight into d_out)
    k_gemm<false, true, true><<<gemm_blocks, 256, GEMM_SMEM>>>(p_t, p_deginv, W2, b2, h2, NN);
    // 7. P = h2 @ Wd1[:128]
    k_gemm<false, false, false><<<gemm_blocks, 256, GEMM_SMEM>>>(h2, nullptr, Wd1, nullptr, p_P, NN);
    // 8. Q = h2 @ Wd1[128:]
    k_gemm<false, false, false><<<gemm_blocks, 256, GEMM_SMEM>>>(h2, nullptr, Wd1 + 128 * 128, nullptr, p_Q, NN);
    // 9/10. decode
    k_decode<<<(NP * 32 + 255) / 256, 256>>>(pos_u, pos_v, (const float4*)p_P, (const float4*)p_Q,
                                             bd1, Wd2, bd2, pos_out, NP);
    k_decode<<<(NP * 32 + 255) / 256, 256>>>(neg_u, neg_v, (const float4*)p_P, (const float4*)p_Q,
                                             bd1, Wd2, bd2, neg_out, NP);
}

// round 2
// speedup vs baseline: 1.0024x; 1.0024x over previous
#include <cuda_runtime.h>
#include <cuda_bf16.h>

// ---------------------------------------------------------------------------
// SparseGraphSAGE on GB300 — round 2.
//   - GEMMs rewritten with packed fp32 (fma.rn.f32x2 / FFMA2) + transposed
//     A-tile in smem (row-pairs contiguous -> LDS.64 gives an f32x2 operand).
//   - GEMM h2 / P / Q fused into one 3-phase kernel (A tile & smem reuse).
//   - pos/neg decode fused into one launch.
// Pipeline: zero_cnt -> build buckets -> spmm(h) -> gemm1(relu) ->
//           spmm(h1) -> gemm3(h2,P,Q fused) -> decode(pos+neg)
// ---------------------------------------------------------------------------

#define NN_MAX 50000
#define CAP 64          // per-row edge capacity; mean deg=16, P(>64) ~ 1e-19

__device__ int   g_cnt[NN_MAX];
__device__ int   g_col[NN_MAX * CAP];
__device__ float g_val[NN_MAX * CAP];
__device__ float g_deginv[NN_MAX];
__device__ __align__(16) float g_t [NN_MAX * 128];
__device__ __align__(16) float g_h1[NN_MAX * 128];
__device__ __align__(16) float g_P [NN_MAX * 128];
__device__ __align__(16) float g_Q [NN_MAX * 128];

// ------------------------------ f32x2 helpers ------------------------------
__device__ __forceinline__ unsigned long long f2_fma(unsigned long long a,
                                                     unsigned long long b,
                                                     unsigned long long c) {
    unsigned long long d;
    asm("fma.rn.f32x2 %0, %1, %2, %3;" : "=l"(d) : "l"(a), "l"(b), "l"(c));
    return d;
}
__device__ __forceinline__ unsigned long long f2_dup(float x) {
    unsigned long long d;
    unsigned xi = __float_as_uint(x);
    asm("mov.b64 %0, {%1, %1};" : "=l"(d) : "r"(xi));
    return d;
}
__device__ __forceinline__ float f2_lo(unsigned long long a) {
    return __uint_as_float((unsigned)a);
}
__device__ __forceinline__ float f2_hi(unsigned long long a) {
    return __uint_as_float((unsigned)(a >> 32));
}

// ------------------------------ smem geometry ------------------------------
// Ws: 128 x 128 (k-major, row-major copy of W)         = 65536 B
// As: 128 x 66  (transposed A tile: As[k*66 + m], pad) = 33792 B
#define AS_PAD 66
#define WS_FLOATS (128 * 128)
#define AS_FLOATS (128 * AS_PAD)
#define GEMM_SMEM_BYTES ((WS_FLOATS + AS_FLOATS) * 4)

__device__ __forceinline__ void load_W(float* Ws, const float* __restrict__ W, int tid) {
    const float4* W4 = (const float4*)W;
    float4* Ws4 = (float4*)Ws;
#pragma unroll
    for (int i = 0; i < 16; i++)
        Ws4[i * 256 + tid] = W4[i * 256 + tid];
}

// Load 64-row A tile into transposed smem layout As[k][m] (conflict-free STS:
// warp lanes vary m with stride 1).
__device__ __forceinline__ void load_A(float* As, const float* __restrict__ A,
                                       const float* __restrict__ scale,
                                       int m_base, int M, int tid) {
    const float4* A4 = (const float4*)A;
#pragma unroll
    for (int i = 0; i < 8; i++) {
        int j  = i * 256 + tid;   // 0..2047
        int c4 = j >> 6;          // k-group 0..31
        int m  = j & 63;          // row in tile
        int gm = m_base + m;
        if (gm >= M) gm = M - 1;
        float4 v = A4[gm * 32 + c4];
        if (scale != nullptr) {
            float s = scale[gm];
            v.x *= s; v.y *= s; v.z *= s; v.w *= s;
        }
        int kb = c4 * 4;
        As[(kb + 0) * AS_PAD + m] = v.x;
        As[(kb + 1) * AS_PAD + m] = v.y;
        As[(kb + 2) * AS_PAD + m] = v.z;
        As[(kb + 3) * AS_PAD + m] = v.w;
    }
}

// Core 64x128x128 MMA: thread (ty,tx) computes rows m0..m0+7 (as 4 row-pairs)
// x cols n0..n0+3. 25 instr / 64 FLOP.
__device__ __forceinline__ void mma_tile(const float* Ws, const float* As,
                                         int m0, int n0,
                                         unsigned long long acc[4][4]) {
#pragma unroll
    for (int rp = 0; rp < 4; rp++)
#pragma unroll
        for (int c = 0; c < 4; c++) acc[rp][c] = 0ull;

#pragma unroll 4
    for (int k = 0; k < 128; k++) {
        float4 w = *(const float4*)&Ws[k * 128 + n0];
        unsigned long long w0 = f2_dup(w.x);
        unsigned long long w1 = f2_dup(w.y);
        unsigned long long w2 = f2_dup(w.z);
        unsigned long long w3 = f2_dup(w.w);
        const float* ar = &As[k * AS_PAD + m0];
        unsigned long long a0 = *(const unsigned long long*)(ar + 0);
        unsigned long long a1 = *(const unsigned long long*)(ar + 2);
        unsigned long long a2 = *(const unsigned long long*)(ar + 4);
        unsigned long long a3 = *(const unsigned long long*)(ar + 6);
        acc[0][0] = f2_fma(a0, w0, acc[0][0]);
        acc[0][1] = f2_fma(a0, w1, acc[0][1]);
        acc[0][2] = f2_fma(a0, w2, acc[0][2]);
        acc[0][3] = f2_fma(a0, w3, acc[0][3]);
        acc[1][0] = f2_fma(a1, w0, acc[1][0]);
        acc[1][1] = f2_fma(a1, w1, acc[1][1]);
        acc[1][2] = f2_fma(a1, w2, acc[1][2]);
        acc[1][3] = f2_fma(a1, w3, acc[1][3]);
        acc[2][0] = f2_fma(a2, w0, acc[2][0]);
        acc[2][1] = f2_fma(a2, w1, acc[2][1]);
        acc[2][2] = f2_fma(a2, w2, acc[2][2]);
        acc[2][3] = f2_fma(a2, w3, acc[2][3]);
        acc[3][0] = f2_fma(a3, w0, acc[3][0]);
        acc[3][1] = f2_fma(a3, w1, acc[3][1]);
        acc[3][2] = f2_fma(a3, w2, acc[3][2]);
        acc[3][3] = f2_fma(a3, w3, acc[3][3]);
    }
}

__device__ __forceinline__ void epilogue(float* __restrict__ C,
                                         const unsigned long long acc[4][4],
                                         const float* __restrict__ bias, bool relu,
                                         int m_base, int m0, int n0, int M) {
    float4 bv = make_float4(0.f, 0.f, 0.f, 0.f);
    if (bias != nullptr) bv = *(const float4*)&bias[n0];
#pragma unroll
    for (int rp = 0; rp < 4; rp++) {
        int r0 = m_base + m0 + 2 * rp;
        float4 lo, hi;
        lo.x = f2_lo(acc[rp][0]) + bv.x;  hi.x = f2_hi(acc[rp][0]) + bv.x;
        lo.y = f2_lo(acc[rp][1]) + bv.y;  hi.y = f2_hi(acc[rp][1]) + bv.y;
        lo.z = f2_lo(acc[rp][2]) + bv.z;  hi.z = f2_hi(acc[rp][2]) + bv.z;
        lo.w = f2_lo(acc[rp][3]) + bv.w;  hi.w = f2_hi(acc[rp][3]) + bv.w;
        if (relu) {
            lo.x = fmaxf(lo.x, 0.f); lo.y = fmaxf(lo.y, 0.f);
            lo.z = fmaxf(lo.z, 0.f); lo.w = fmaxf(lo.w, 0.f);
            hi.x = fmaxf(hi.x, 0.f); hi.y = fmaxf(hi.y, 0.f);
            hi.z = fmaxf(hi.z, 0.f); hi.w = fmaxf(hi.w, 0.f);
        }
        if (r0 < M)     *(float4*)&C[r0 * 128 + n0]       = lo;
        if (r0 + 1 < M) *(float4*)&C[(r0 + 1) * 128 + n0] = hi;
    }
}

// -------------------------------- gemm1 ------------------------------------
// h1 = relu((t * deginv) @ W1 + b1)
__global__ void k_gemm1(const float* __restrict__ A, const float* __restrict__ scale,
                        const float* __restrict__ W, const float* __restrict__ bias,
                        float* __restrict__ C, int M) {
    extern __shared__ float sm[];
    float* Ws = sm;
    float* As = sm + WS_FLOATS;
    int tid = threadIdx.x;
    int m_base = blockIdx.x * 64;
    int tx = tid & 31, ty = tid >> 5;
    int n0 = tx * 4, m0 = ty * 8;

    load_W(Ws, W, tid);
    load_A(As, A, scale, m_base, M, tid);
    __syncthreads();

    unsigned long long acc[4][4];
    mma_tile(Ws, As, m0, n0, acc);
    epilogue(C, acc, bias, true, m_base, m0, n0, M);
}

// -------------------------- fused h2 / P / Q --------------------------------
// phase 1: h2 = (t*deginv) @ W2 + b2   (written to gmem)
// phase 2: P  = h2 @ Wd1[:128]
// phase 3: Q  = h2 @ Wd1[128:]         (A tile reused from phase 2)
__global__ void k_gemm3(const float* __restrict__ A, const float* __restrict__ scale,
                        const float* __restrict__ W2, const float* __restrict__ b2,
                        float* __restrict__ H2,
                        const float* __restrict__ Wd1,
                        float* __restrict__ P, float* __restrict__ Q, int M) {
    extern __shared__ float sm[];
    float* Ws = sm;
    float* As = sm + WS_FLOATS;
    int tid = threadIdx.x;
    int m_base = blockIdx.x * 64;
    int tx = tid & 31, ty = tid >> 5;
    int n0 = tx * 4, m0 = ty * 8;

    unsigned long long acc[4][4];

    // phase 1: h2
    load_W(Ws, W2, tid);
    load_A(As, A, scale, m_base, M, tid);
    __syncthreads();
    mma_tile(Ws, As, m0, n0, acc);
    epilogue(H2, acc, b2, false, m_base, m0, n0, M);
    __syncthreads();

    // phase 2: P = h2 @ Wd1_top  (h2 written by this block, visible after sync)
    load_W(Ws, Wd1, tid);
    load_A(As, H2, nullptr, m_base, M, tid);
    __syncthreads();
    mma_tile(Ws, As, m0, n0, acc);
    epilogue(P, acc, nullptr, false, m_base, m0, n0, M);
    __syncthreads();

    // phase 3: Q = h2 @ Wd1_bot  (As already holds h2 tile)
    load_W(Ws, Wd1 + 128 * 128, tid);
    __syncthreads();
    mma_tile(Ws, As, m0, n0, acc);
    epilogue(Q, acc, nullptr, false, m_base, m0, n0, M);
}

// -------------------------------- zero counters ---------------------------
__global__ void k_zero_cnt(int nn) {
    int i = blockIdx.x * blockDim.x + threadIdx.x;
    if (i < nn) g_cnt[i] = 0;
}

// -------------------------------- bucket scatter --------------------------
__global__ void k_build(const int2* __restrict__ idx, const float* __restrict__ val, int ne) {
    int e = blockIdx.x * blockDim.x + threadIdx.x;
    if (e >= ne) return;
    int2 rc = idx[e];
    float v = val[e];
    int slot = atomicAdd(&g_cnt[rc.x], 1);
    if (slot < CAP) {
        g_col[rc.x * CAP + slot] = rc.y;
        g_val[rc.x * CAP + slot] = v;
    }
}

// -------------------------------- spmm gather -----------------------------
__global__ void k_spmm(const float4* __restrict__ X, float4* __restrict__ Y,
                       float* __restrict__ deginv_out, int nn) {
    int w = (blockIdx.x * blockDim.x + threadIdx.x) >> 5;
    int lane = threadIdx.x & 31;
    if (w >= nn) return;
    int cnt = g_cnt[w];
    if (cnt > CAP) cnt = CAP;
    const int*   cols = &g_col[w * CAP];
    const float* vals = &g_val[w * CAP];
    float4 acc = make_float4(0.f, 0.f, 0.f, 0.f);
    float dsum = 0.f;
#pragma unroll 2
    for (int e = 0; e < cnt; e++) {
        int c = cols[e];
        float v = vals[e];
        float4 x = X[c * 32 + lane];
        acc.x += v * x.x; acc.y += v * x.y; acc.z += v * x.z; acc.w += v * x.w;
        dsum += v;
    }
    Y[w * 32 + lane] = acc;
    if (deginv_out != nullptr && lane == 0)
        deginv_out[w] = 1.0f / fmaxf(dsum, 1.0f);
}

// -------------------------------- decoder (pos+neg fused) ------------------
__global__ void k_decode2(const int* __restrict__ pu, const int* __restrict__ pv,
                          const int* __restrict__ nu, const int* __restrict__ nv,
                          const float4* __restrict__ P, const float4* __restrict__ Q,
                          const float* __restrict__ bd1, const float* __restrict__ Wd2,
                          const float* __restrict__ bd2, float* __restrict__ out, int NP) {
    int w = (blockIdx.x * blockDim.x + threadIdx.x) >> 5;
    int lane = threadIdx.x & 31;
    if (w >= 2 * NP) return;
    int u, v;
    if (w < NP) { u = pu[w]; v = pv[w]; }
    else        { u = nu[w - NP]; v = nv[w - NP]; }
    float4 p = P[u * 32 + lane];
    float4 q = Q[v * 32 + lane];
    float4 b = ((const float4*)bd1)[lane];
    float4 d = ((const float4*)Wd2)[lane];
    float h0 = fmaxf(p.x + q.x + b.x, 0.f);
    float h1 = fmaxf(p.y + q.y + b.y, 0.f);
    float h2 = fmaxf(p.z + q.z + b.z, 0.f);
    float h3 = fmaxf(p.w + q.w + b.w, 0.f);
    float s = h0 * d.x + h1 * d.y + h2 * d.z + h3 * d.w;
#pragma unroll
    for (int o = 16; o > 0; o >>= 1)
        s += __shfl_down_sync(0xffffffff, s, o);
    if (lane == 0) out[w] = s + bd2[0];
}

// -------------------------------- launcher --------------------------------
extern "C" void kernel_launch(void* const* d_in, const int* in_sizes, int n_in,
                              void* d_out, int out_size) {
    int o = (n_in >= 16) ? 1 : 0;   // num_nodes scalar present?

    const int2*  adj   = (const int2*) d_in[0];
    const float* avals = (const float*)d_in[1];
    const float* h     = (const float*)d_in[2 + o];
    const int*   pos_u = (const int*)  d_in[3 + o];
    const int*   pos_v = (const int*)  d_in[4 + o];
    const int*   neg_u = (const int*)  d_in[5 + o];
    const int*   neg_v = (const int*)  d_in[6 + o];
    const float* W1    = (const float*)d_in[7 + o];
    const float* b1    = (const float*)d_in[8 + o];
    const float* W2    = (const float*)d_in[9 + o];
    const float* b2    = (const float*)d_in[10 + o];
    const float* Wd1   = (const float*)d_in[11 + o];
    const float* bd1   = (const float*)d_in[12 + o];
    const float* Wd2   = (const float*)d_in[13 + o];
    const float* bd2   = (const float*)d_in[14 + o];

    const int NE = in_sizes[1];
    const int NN = in_sizes[2 + o] / 128;
    const int NP = in_sizes[3 + o];

    float* out = (float*)d_out;
    float* pos_out = out;           // decode writes pos then neg contiguously
    float* h2      = out + 2 * NP;  // [NN,128]

    static float* p_t = nullptr;
    static float* p_h1 = nullptr;
    static float* p_P = nullptr;
    static float* p_Q = nullptr;
    static float* p_deginv = nullptr;
    static bool init = false;
    if (!init) {
        cudaGetSymbolAddress((void**)&p_t, g_t);
        cudaGetSymbolAddress((void**)&p_h1, g_h1);
        cudaGetSymbolAddress((void**)&p_P, g_P);
        cudaGetSymbolAddress((void**)&p_Q, g_Q);
        cudaGetSymbolAddress((void**)&p_deginv, g_deginv);
        cudaFuncSetAttribute(k_gemm1, cudaFuncAttributeMaxDynamicSharedMemorySize, GEMM_SMEM_BYTES);
        cudaFuncSetAttribute(k_gemm3, cudaFuncAttributeMaxDynamicSharedMemorySize, GEMM_SMEM_BYTES);
        init = true;
    }

    int gemm_blocks = (NN + 63) / 64;

    k_zero_cnt<<<(NN + 255) / 256, 256>>>(NN);
    k_build<<<(NE + 255) / 256, 256>>>(adj, avals, NE);
    k_spmm<<<(NN * 32 + 255) / 256, 256>>>((const float4*)h, (float4*)p_t, p_deginv, NN);
    k_gemm1<<<gemm_blocks, 256, GEMM_SMEM_BYTES>>>(p_t, p_deginv, W1, b1, p_h1, NN);
    k_spmm<<<(NN * 32 + 255) / 256, 256>>>((const float4*)p_h1, (float4*)p_t, nullptr, NN);
    k_gemm3<<<gemm_blocks, 256, GEMM_SMEM_BYTES>>>(p_t, p_deginv, W2, b2, h2, Wd1, p_P, p_Q, NN);
    k_decode2<<<(2 * NP * 32 + 255) / 256, 256>>>(pos_u, pos_v, neg_u, neg_v,
                                                  (const float4*)p_P, (const float4*)p_Q,
                                                  bd1, Wd2, bd2, pos_out, NP);
}